// round 11
// baseline (speedup 1.0000x reference)
#include <cuda_runtime.h>
#include <cuda_bf16.h>
#include <cstdint>

#define B_  4
#define N_  4096
#define M1_ 2048
#define M2_ 512
#define F1_ 64
#define F2_ 128
#define F3_ 1024
#define LF_ 64
#define MAXNBR 128

// grid constants (fixed range, row-major cells) shared by FPS and SA pruning
#define GRID_LO   (-18.0f)
#define GRID_INV  (16.0f / 36.0f)

// ---------------- device scratch ----------------
__device__ float g_p1  [B_ * N_  * F1_];
__device__ float g_h1  [B_ * M1_ * F1_];
__device__ float g_ctr1[B_ * M1_ * 2];
__device__ float g_p2  [B_ * M1_ * F2_];
__device__ float g_h2  [B_ * M2_ * F2_];
__device__ float g_ctr2[B_ * M2_ * 2];
__device__ float g_pmax[B_ * 8 * F3_];
// exported bucket sort (level 0: x points, level 1: ctr1 points)
__device__ float          g_sxl[2][B_][N_];
__device__ float          g_syl[2][B_][N_];
__device__ unsigned short g_sil[2][B_][N_];
__device__ int            g_cel[2][B_][256];

// ------ fused: lf = tanh(tanh(x W1+b1) W2+b2);  p1 = [lf,z] @ c1W[:65]+c1b
__global__ void lfp1_kernel(const float* __restrict__ x, const float* __restrict__ zones,
                            const float* __restrict__ W1, const float* __restrict__ b1,
                            const float* __restrict__ W2, const float* __restrict__ b2,
                            const float* __restrict__ c1W, const float* __restrict__ c1b,
                            float* __restrict__ lf_out) {
    __shared__ float sW2[64 * 64];
    __shared__ float sWc[65 * 64];
    __shared__ float sW1[2 * 64];
    __shared__ float sb1[64], sb2[64], sbc[64];
    __shared__ float st1[64], slf[64];
    int tid = threadIdx.x;  // 64
    for (int i = tid; i < 64 * 64; i += 64) sW2[i] = W2[i];
    for (int i = tid; i < 65 * 64; i += 64) sWc[i] = c1W[i];
    sW1[tid] = W1[tid]; sW1[64 + tid] = W1[64 + tid];
    sb1[tid] = b1[tid]; sb2[tid] = b2[tid]; sbc[tid] = c1b[tid];
    __syncthreads();
    int row0 = blockIdx.x * 32;
    for (int r = 0; r < 32; r++) {
        int row = row0 + r;
        float x0 = x[row * 2], x1 = x[row * 2 + 1];
        float t1 = tanhf(x0 * sW1[tid] + x1 * sW1[64 + tid] + sb1[tid]);
        st1[tid] = t1;
        __syncthreads();
        float acc = sb2[tid];
#pragma unroll
        for (int c = 0; c < 64; c++) acc = fmaf(st1[c], sW2[c * 64 + tid], acc);
        float lf = tanhf(acc);
        lf_out[row * 64 + tid] = lf;
        slf[tid] = lf;
        __syncthreads();
        float z = zones[row];
        float acc2 = fmaf(z, sWc[64 * 64 + tid], sbc[tid]);
#pragma unroll
        for (int c = 0; c < 64; c++) acc2 = fmaf(slf[c], sWc[c * 64 + tid], acc2);
        g_p1[row * 64 + tid] = acc2;
        __syncthreads();
    }
}

// ---------------- FPS: bucketed + TWO pruning regions per warp ------------
// T=512 chain (measured 313 cyc/iter) with T=1024-grade pruning: each warp
// owns two disjoint contiguous sorted regions (A,B), each with its own bbox
// and cached warp (max value, min ORIGINAL index) tuple. Per iteration a
// region is re-reduced only if its bbox lower bound beats its cached max
// (skip provably leaves every md in the region unchanged). The two cached
// tuples are combined locally (max value, min index on tie) before one
// STS.64 per warp; level-2 merge is the proven redundant all-warp redux.
// Winner sequence is bitwise identical to jnp.argmax-based sequential FPS.
template <int T, int P, int N, int M, int LEVEL>
__global__ __launch_bounds__(T, 1) void fps_kernel(const float* __restrict__ pos_in) {
    const int NW = T / 32;
    const int PH = P / 2;                  // points per thread per region
    const unsigned FULL = 0xFFFFFFFFu;
    int b = blockIdx.x;
    int tid = threadIdx.x;
    int wid = tid >> 5, lane = tid & 31;
    const float2* p = (LEVEL == 0) ? (const float2*)(pos_in + (size_t)b * N * 2)
                                   : (const float2*)(g_ctr1 + (size_t)b * N * 2);
    float* cout = (LEVEL == 0) ? (g_ctr1 + (size_t)b * M * 2)
                               : (g_ctr2 + (size_t)b * M * 2);

    __shared__ float2 sxy[N];               // ORIGINAL order (winner lookup)
    __shared__ float spx[N], spy[N];        // sorted (init only)
    __shared__ unsigned short ssidx[N];     // sorted -> original idx
    __shared__ int counts[256], offs[256], cursor[256];
    __shared__ unsigned long long sVI[2][NW];

    // ---- load raw, publish original-order table ----
    float rx[P], ry[P];
    int cid[P];
#pragma unroll
    for (int k = 0; k < P; k++) {
        float2 v = p[tid + k * T];
        rx[k] = v.x; ry[k] = v.y;
        sxy[tid + k * T] = v;
    }
    if (tid < 256) counts[tid] = 0;
    __syncthreads();
#pragma unroll
    for (int k = 0; k < P; k++) {
        int cx = (int)fminf(fmaxf((rx[k] - GRID_LO) * GRID_INV, 0.f), 15.f);
        int cy = (int)fminf(fmaxf((ry[k] - GRID_LO) * GRID_INV, 0.f), 15.f);
        cid[k] = cy * 16 + cx;
        atomicAdd(&counts[cid[k]], 1);
    }
    __syncthreads();
    if (tid < 256) offs[tid] = counts[tid];
    __syncthreads();
    for (int d = 1; d < 256; d <<= 1) {
        int v = 0;
        if (tid < 256 && tid >= d) v = offs[tid - d];
        __syncthreads();
        if (tid < 256 && tid >= d) offs[tid] += v;
        __syncthreads();
    }
    if (tid < 256) cursor[tid] = offs[tid] - counts[tid];
    __syncthreads();
#pragma unroll
    for (int k = 0; k < P; k++) {
        int pos = atomicAdd(&cursor[cid[k]], 1);
        spx[pos] = rx[k]; spy[pos] = ry[k];
        ssidx[pos] = (unsigned short)(tid + k * T);
    }
    __syncthreads();

    // ---- export bucket sort for SA pruning (one-time) ----
    for (int i = tid; i < N; i += T) {
        g_sxl[LEVEL][b][i] = spx[i];
        g_syl[LEVEL][b][i] = spy[i];
        g_sil[LEVEL][b][i] = ssidx[i];
    }
    if (tid < 256) g_cel[LEVEL][b][tid] = offs[tid];  // inclusive prefix = cell end

    // ---- registers: two per-warp regions + per-region bboxes ----
    float pxA[PH], pyA[PH], mdA[PH];
    float pxB[PH], pyB[PH], mdB[PH];
    unsigned siA[PH], siB[PH];
    int segA = wid * 32 * P + lane * PH;
    int segB = segA + 32 * PH;
    float ax0 = 1e30f, ax1 = -1e30f, ay0 = 1e30f, ay1 = -1e30f;
    float bx0 = 1e30f, bx1 = -1e30f, by0 = 1e30f, by1 = -1e30f;
#pragma unroll
    for (int k = 0; k < PH; k++) {
        pxA[k] = spx[segA + k]; pyA[k] = spy[segA + k];
        siA[k] = (unsigned)ssidx[segA + k];
        mdA[k] = 1e10f;
        ax0 = fminf(ax0, pxA[k]); ax1 = fmaxf(ax1, pxA[k]);
        ay0 = fminf(ay0, pyA[k]); ay1 = fmaxf(ay1, pyA[k]);
        pxB[k] = spx[segB + k]; pyB[k] = spy[segB + k];
        siB[k] = (unsigned)ssidx[segB + k];
        mdB[k] = 1e10f;
        bx0 = fminf(bx0, pxB[k]); bx1 = fmaxf(bx1, pxB[k]);
        by0 = fminf(by0, pyB[k]); by1 = fmaxf(by1, pyB[k]);
    }
#pragma unroll
    for (int o = 16; o > 0; o >>= 1) {
        ax0 = fminf(ax0, __shfl_xor_sync(FULL, ax0, o));
        ax1 = fmaxf(ax1, __shfl_xor_sync(FULL, ax1, o));
        ay0 = fminf(ay0, __shfl_xor_sync(FULL, ay0, o));
        ay1 = fmaxf(ay1, __shfl_xor_sync(FULL, ay1, o));
        bx0 = fminf(bx0, __shfl_xor_sync(FULL, bx0, o));
        bx1 = fmaxf(bx1, __shfl_xor_sync(FULL, bx1, o));
        by0 = fminf(by0, __shfl_xor_sync(FULL, by0, o));
        by1 = fmaxf(by1, __shfl_xor_sync(FULL, by1, o));
    }
    __syncthreads();

    float2 c0 = sxy[0];
    float lx = c0.x, ly = c0.y;
    if (tid == 0) { cout[0] = lx; cout[1] = ly; }

    // cached per-region warp tuples (uniform across lanes)
    unsigned wvA = __float_as_uint(1e10f), wiA = 0u;
    unsigned wvB = __float_as_uint(1e10f), wiB = 0u;
    float wvAf = 1e10f, wvBf = 1e10f;

    for (int t = 1; t < M; t++) {
        float exA = fmaxf(fmaxf(ax0 - lx, lx - ax1), 0.f);
        float eyA = fmaxf(fmaxf(ay0 - ly, ly - ay1), 0.f);
        float lbA = fmaf(exA, exA, eyA * eyA);
        float exB = fmaxf(fmaxf(bx0 - lx, lx - bx1), 0.f);
        float eyB = fmaxf(fmaxf(by0 - ly, ly - by1), 0.f);
        float lbB = fmaf(exB, exB, eyB * eyB);
        if (lbA < wvAf) {   // uniform per-warp branch (region A)
            float tb = -1.f;
#pragma unroll
            for (int k = 0; k < PH; k++) {
                float dx = pxA[k] - lx, dy = pyA[k] - ly;
                float d2 = fmaf(dx, dx, dy * dy);
                mdA[k] = fminf(mdA[k], d2);
                tb = fmaxf(tb, mdA[k]);
            }
            unsigned bi = 0xFFFFFFFFu;
#pragma unroll
            for (int k = 0; k < PH; k++)
                if (mdA[k] == tb && siA[k] < bi) bi = siA[k];
            unsigned vb = __float_as_uint(tb);
            unsigned wm = __reduce_max_sync(FULL, vb);
            wiA = __reduce_min_sync(FULL, (vb == wm) ? bi : 0xFFFFFFFFu);
            wvA = wm; wvAf = __uint_as_float(wm);
        }
        if (lbB < wvBf) {   // uniform per-warp branch (region B)
            float tb = -1.f;
#pragma unroll
            for (int k = 0; k < PH; k++) {
                float dx = pxB[k] - lx, dy = pyB[k] - ly;
                float d2 = fmaf(dx, dx, dy * dy);
                mdB[k] = fminf(mdB[k], d2);
                tb = fmaxf(tb, mdB[k]);
            }
            unsigned bi = 0xFFFFFFFFu;
#pragma unroll
            for (int k = 0; k < PH; k++)
                if (mdB[k] == tb && siB[k] < bi) bi = siB[k];
            unsigned vb = __float_as_uint(tb);
            unsigned wm = __reduce_max_sync(FULL, vb);
            wiB = __reduce_min_sync(FULL, (vb == wm) ? bi : 0xFFFFFFFFu);
            wvB = wm; wvBf = __uint_as_float(wm);
        }
        // combine two cached region tuples (max value, min index on tie)
        unsigned cv, ci;
        if (wvA > wvB)      { cv = wvA; ci = wiA; }
        else if (wvB > wvA) { cv = wvB; ci = wiB; }
        else                { cv = wvA; ci = min(wiA, wiB); }
        int buf = t & 1;
        if (lane == 0)
            sVI[buf][wid] = ((unsigned long long)cv << 32) | ci;
        __syncthreads();
        unsigned long long e;
        if (NW == 32) e = sVI[buf][lane];
        else          e = (lane < NW) ? sVI[buf][lane] : 0ull;
        unsigned v2 = (unsigned)(e >> 32), i2 = (unsigned)e;
        unsigned m2 = __reduce_max_sync(FULL, v2);
        unsigned c2 = (v2 == m2) ? i2 : 0xFFFFFFFFu;
        unsigned gi = __reduce_min_sync(FULL, c2);
        float2 w = sxy[gi];          // broadcast LDS.64
        lx = w.x; ly = w.y;
        if (tid == 0) { cout[t * 2] = lx; cout[t * 2 + 1] = ly; }
    }
}

// ---------------- SA1: grid-pruned radius scan + max-aggregate ------------
__global__ void sa1_kernel(const float* __restrict__ c1W) {
    const int M = M1_, F = F1_;
    const float R = 0.5f, R2 = 0.25f;
    int i = blockIdx.x, b = blockIdx.y, tid = threadIdx.x;  // 64 threads
    __shared__ float sdx[MAXNBR], sdy[MAXNBR];
    __shared__ int   snb[MAXNBR];
    __shared__ int   scnt;
    if (tid == 0) scnt = 0;
    __syncthreads();
    float cx = g_ctr1[(b * M + i) * 2], cy = g_ctr1[(b * M + i) * 2 + 1];
    int ix0 = max(0, (int)((cx - R - GRID_LO) * GRID_INV));
    int ix1 = min(15, (int)((cx + R - GRID_LO) * GRID_INV));
    int iy0 = max(0, (int)((cy - R - GRID_LO) * GRID_INV));
    int iy1 = min(15, (int)((cy + R - GRID_LO) * GRID_INV));
    for (int gy = iy0; gy <= iy1; gy++) {
        int c0 = gy * 16 + ix0, c1 = gy * 16 + ix1;
        int s = (c0 == 0) ? 0 : g_cel[0][b][c0 - 1];
        int e = g_cel[0][b][c1];
        for (int j = s + tid; j < e; j += 64) {
            float dx = g_sxl[0][b][j] - cx;
            float dy = g_syl[0][b][j] - cy;
            float d2 = fmaf(dx, dx, dy * dy);
            if (d2 <= R2) {
                int s2 = atomicAdd(&scnt, 1);
                if (s2 < MAXNBR) {
                    snb[s2] = (int)g_sil[0][b][j];
                    sdx[s2] = dx; sdy[s2] = dy;
                }
            }
        }
    }
    __syncthreads();
    int cnt = min(scnt, MAXNBR);
    float wx = c1W[65 * 64 + tid];
    float wy = c1W[66 * 64 + tid];
    float mx = -1e9f;
    const float* pb = g_p1 + (size_t)b * N_ * F;
    int n = 0;
    for (; n + 4 <= cnt; n += 4) {
        float v0 = pb[snb[n] * F + tid];
        float v1 = pb[snb[n + 1] * F + tid];
        float v2 = pb[snb[n + 2] * F + tid];
        float v3 = pb[snb[n + 3] * F + tid];
        float m0 = fmaf(sdx[n], wx, fmaf(sdy[n], wy, v0));
        float m1 = fmaf(sdx[n + 1], wx, fmaf(sdy[n + 1], wy, v1));
        float m2 = fmaf(sdx[n + 2], wx, fmaf(sdy[n + 2], wy, v2));
        float m3 = fmaf(sdx[n + 3], wx, fmaf(sdy[n + 3], wy, v3));
        mx = fmaxf(mx, fmaxf(fmaxf(m0, m1), fmaxf(m2, m3)));
    }
    for (; n < cnt; n++) {
        float m = fmaf(sdx[n], wx, fmaf(sdy[n], wy, pb[snb[n] * F + tid]));
        mx = fmaxf(mx, m);
    }
    g_h1[((size_t)b * M + i) * F + tid] = mx;
}

// ---------------- p2[j] = h1_j @ c2W[:64] + c2b ---------------------------
__global__ void p2_kernel(const float* __restrict__ c2W, const float* __restrict__ c2b) {
    __shared__ float sW[64 * 128];
    __shared__ float sb[128];
    __shared__ float srow[64];
    int tid = threadIdx.x;  // 128
    for (int i = tid; i < 64 * 128; i += 128) sW[i] = c2W[i];
    sb[tid] = c2b[tid];
    __syncthreads();
    int row0 = blockIdx.x * 32;
    for (int r = 0; r < 32; r++) {
        int row = row0 + r;
        if (tid < 64) srow[tid] = g_h1[row * 64 + tid];
        __syncthreads();
        float acc = sb[tid];
#pragma unroll
        for (int c = 0; c < 64; c++) acc = fmaf(srow[c], sW[c * 128 + tid], acc);
        g_p2[row * 128 + tid] = acc;
        __syncthreads();
    }
}

// ---------------- SA2: grid-pruned (r=1.0 over ctr1 via FPS2's sort) ------
__global__ void sa2_kernel(const float* __restrict__ c2W) {
    const int M = M2_, F = F2_;
    const float R = 1.0f, R2 = 1.0f;
    int i = blockIdx.x, b = blockIdx.y, tid = threadIdx.x;  // 128
    __shared__ float sdx[MAXNBR], sdy[MAXNBR];
    __shared__ int   snb[MAXNBR];
    __shared__ int   scnt;
    if (tid == 0) scnt = 0;
    __syncthreads();
    float cx = g_ctr2[(b * M + i) * 2], cy = g_ctr2[(b * M + i) * 2 + 1];
    int ix0 = max(0, (int)((cx - R - GRID_LO) * GRID_INV));
    int ix1 = min(15, (int)((cx + R - GRID_LO) * GRID_INV));
    int iy0 = max(0, (int)((cy - R - GRID_LO) * GRID_INV));
    int iy1 = min(15, (int)((cy + R - GRID_LO) * GRID_INV));
    for (int gy = iy0; gy <= iy1; gy++) {
        int c0 = gy * 16 + ix0, c1 = gy * 16 + ix1;
        int s = (c0 == 0) ? 0 : g_cel[1][b][c0 - 1];
        int e = g_cel[1][b][c1];
        for (int j = s + tid; j < e; j += F) {
            float dx = g_sxl[1][b][j] - cx;
            float dy = g_syl[1][b][j] - cy;
            float d2 = fmaf(dx, dx, dy * dy);
            if (d2 <= R2) {
                int s2 = atomicAdd(&scnt, 1);
                if (s2 < MAXNBR) {
                    snb[s2] = (int)g_sil[1][b][j];
                    sdx[s2] = dx; sdy[s2] = dy;
                }
            }
        }
    }
    __syncthreads();
    int cnt = min(scnt, MAXNBR);
    float wx = c2W[64 * 128 + tid];
    float wy = c2W[65 * 128 + tid];
    float mx = -1e9f;
    const float* pb = g_p2 + (size_t)b * M1_ * F;
    int n = 0;
    for (; n + 4 <= cnt; n += 4) {
        float v0 = pb[snb[n] * F + tid];
        float v1 = pb[snb[n + 1] * F + tid];
        float v2 = pb[snb[n + 2] * F + tid];
        float v3 = pb[snb[n + 3] * F + tid];
        float m0 = fmaf(sdx[n], wx, fmaf(sdy[n], wy, v0));
        float m1 = fmaf(sdx[n + 1], wx, fmaf(sdy[n + 1], wy, v1));
        float m2 = fmaf(sdx[n + 2], wx, fmaf(sdy[n + 2], wy, v2));
        float m3 = fmaf(sdx[n + 3], wx, fmaf(sdy[n + 3], wy, v3));
        mx = fmaxf(mx, fmaxf(fmaxf(m0, m1), fmaxf(m2, m3)));
    }
    for (; n < cnt; n++) {
        float m = fmaf(sdx[n], wx, fmaf(sdy[n], wy, pb[snb[n] * F + tid]));
        mx = fmaxf(mx, m);
    }
    g_h2[((size_t)b * M + i) * F + tid] = mx;
}

// ---------------- final projection + partial max pool ---------------------
__global__ void final_partial(const float* __restrict__ W, const float* __restrict__ bias) {
    int fchunk = blockIdx.x, rchunk = blockIdx.y, b = blockIdx.z;
    int tid = threadIdx.x;  // 128
    int f = fchunk * 128 + tid;
    __shared__ float sh[64][132];
    int r0 = rchunk * 64;
    for (int e = tid; e < 64 * 130; e += 128) {
        int r = e / 130, c = e % 130;
        float v;
        if (c < 128) v = g_h2[((size_t)b * M2_ + r0 + r) * 128 + c];
        else         v = g_ctr2[(b * M2_ + r0 + r) * 2 + (c - 128)];
        sh[r][c] = v;
    }
    __syncthreads();
    float acc[64];
#pragma unroll
    for (int r = 0; r < 64; r++) acc[r] = 0.0f;
    for (int c = 0; c < 130; c++) {
        float w = W[c * 1024 + f];
#pragma unroll
        for (int r = 0; r < 64; r++) acc[r] = fmaf(sh[r][c], w, acc[r]);
    }
    float mx = acc[0];
#pragma unroll
    for (int r = 1; r < 64; r++) mx = fmaxf(mx, acc[r]);
    g_pmax[(b * 8 + rchunk) * 1024 + f] = mx + bias[f];
}

__global__ void final_reduce(float* __restrict__ gf) {
    int b = blockIdx.x, f = threadIdx.x;  // 1024
    float mx = g_pmax[(b * 8) * 1024 + f];
#pragma unroll
    for (int r = 1; r < 8; r++) mx = fmaxf(mx, g_pmax[(b * 8 + r) * 1024 + f]);
    gf[b * 1024 + f] = mx;
}

// ---------------- launch ---------------------------------------------------
extern "C" void kernel_launch(void* const* d_in, const int* in_sizes, int n_in,
                              void* d_out, int out_size) {
    const float* x     = (const float*)d_in[0];
    const float* zones = (const float*)d_in[1];
    const float* lf_W1 = (const float*)d_in[2];
    const float* lf_b1 = (const float*)d_in[3];
    const float* lf_W2 = (const float*)d_in[4];
    const float* lf_b2 = (const float*)d_in[5];
    const float* c1_W  = (const float*)d_in[6];
    const float* c1_b  = (const float*)d_in[7];
    const float* c2_W  = (const float*)d_in[8];
    const float* c2_b  = (const float*)d_in[9];
    const float* c3_W  = (const float*)d_in[10];
    const float* c3_b  = (const float*)d_in[11];

    float* lf_out = (float*)d_out;
    float* gf_out = (float*)d_out + (size_t)B_ * N_ * LF_;

    fps_kernel<512, 8, N_, M1_, 0><<<B_, 512>>>(x);         // FPS L1: 2x128pt regions/warp
    lfp1_kernel<<<(B_ * N_) / 32, 64>>>(x, zones, lf_W1, lf_b1, lf_W2, lf_b2,
                                        c1_W, c1_b, lf_out);
    fps_kernel<512, 4, M1_, M2_, 1><<<B_, 512>>>(nullptr);  // FPS L2: 2x64pt regions/warp
    sa1_kernel<<<dim3(M1_, B_), 64>>>(c1_W);
    p2_kernel<<<(B_ * M1_) / 32, 128>>>(c2_W, c2_b);
    sa2_kernel<<<dim3(M2_, B_), F2_>>>(c2_W);
    final_partial<<<dim3(8, 8, B_), 128>>>(c3_W, c3_b);
    final_reduce<<<B_, 1024>>>(gf_out);
}

// round 12
// speedup vs baseline: 1.4400x; 1.4400x over previous
#include <cuda_runtime.h>
#include <cuda_bf16.h>
#include <cstdint>

#define B_  4
#define N_  4096
#define M1_ 2048
#define M2_ 512
#define F1_ 64
#define F2_ 128
#define F3_ 1024
#define LF_ 64
#define MAXNBR 128

// grid constants (fixed range, row-major cells) shared by FPS and SA pruning
#define GRID_LO   (-18.0f)
#define GRID_INV  (16.0f / 36.0f)

// ---------------- device scratch ----------------
__device__ float g_p1  [B_ * N_  * F1_];
__device__ float g_h1  [B_ * M1_ * F1_];
__device__ float g_ctr1[B_ * M1_ * 2];
__device__ float g_p2  [B_ * M1_ * F2_];
__device__ float g_h2  [B_ * M2_ * F2_];
__device__ float g_ctr2[B_ * M2_ * 2];
__device__ float g_pmax[B_ * 8 * F3_];
// exported bucket sort (level 0: x points, level 1: ctr1 points)
__device__ float          g_sxl[2][B_][N_];
__device__ float          g_syl[2][B_][N_];
__device__ unsigned short g_sil[2][B_][N_];
__device__ int            g_cel[2][B_][256];

// ------ fused: lf = tanh(tanh(x W1+b1) W2+b2);  p1 = [lf,z] @ c1W[:65]+c1b
__global__ void lfp1_kernel(const float* __restrict__ x, const float* __restrict__ zones,
                            const float* __restrict__ W1, const float* __restrict__ b1,
                            const float* __restrict__ W2, const float* __restrict__ b2,
                            const float* __restrict__ c1W, const float* __restrict__ c1b,
                            float* __restrict__ lf_out) {
    __shared__ float sW2[64 * 64];
    __shared__ float sWc[65 * 64];
    __shared__ float sW1[2 * 64];
    __shared__ float sb1[64], sb2[64], sbc[64];
    __shared__ float st1[64], slf[64];
    int tid = threadIdx.x;  // 64
    for (int i = tid; i < 64 * 64; i += 64) sW2[i] = W2[i];
    for (int i = tid; i < 65 * 64; i += 64) sWc[i] = c1W[i];
    sW1[tid] = W1[tid]; sW1[64 + tid] = W1[64 + tid];
    sb1[tid] = b1[tid]; sb2[tid] = b2[tid]; sbc[tid] = c1b[tid];
    __syncthreads();
    int row0 = blockIdx.x * 32;
    for (int r = 0; r < 32; r++) {
        int row = row0 + r;
        float x0 = x[row * 2], x1 = x[row * 2 + 1];
        float t1 = tanhf(x0 * sW1[tid] + x1 * sW1[64 + tid] + sb1[tid]);
        st1[tid] = t1;
        __syncthreads();
        float acc = sb2[tid];
#pragma unroll
        for (int c = 0; c < 64; c++) acc = fmaf(st1[c], sW2[c * 64 + tid], acc);
        float lf = tanhf(acc);
        lf_out[row * 64 + tid] = lf;
        slf[tid] = lf;
        __syncthreads();
        float z = zones[row];
        float acc2 = fmaf(z, sWc[64 * 64 + tid], sbc[tid]);
#pragma unroll
        for (int c = 0; c < 64; c++) acc2 = fmaf(slf[c], sWc[c * 64 + tid], acc2);
        g_p1[row * 64 + tid] = acc2;
        __syncthreads();
    }
}

// ---------------- FPS: bucketed + warp bbox prune + redundant redux merge --
// (R6 form — the measured optimum: one region per warp, one barrier per
// iteration, all warps redundantly perform the level-2 merge, winner coords
// via broadcast LDS from the original-order table.)
// Exact vs jnp.argmax: skipped warp updates are provably no-ops (bbox lower
// bound >= cached warp max); all reductions are (max value, min ORIGINAL
// index) -> identical first-occurrence winner.
// Exports the bucket sort for SA grid pruning. sVI has 32 slots zero-inited
// so the merge load needs no lane predicate at any NW.
template <int T, int P, int N, int M, int LEVEL>
__global__ __launch_bounds__(T, 1) void fps_kernel(const float* __restrict__ pos_in) {
    const unsigned FULL = 0xFFFFFFFFu;
    int b = blockIdx.x;
    int tid = threadIdx.x;
    int wid = tid >> 5, lane = tid & 31;
    const float2* p = (LEVEL == 0) ? (const float2*)(pos_in + (size_t)b * N * 2)
                                   : (const float2*)(g_ctr1 + (size_t)b * N * 2);
    float* cout = (LEVEL == 0) ? (g_ctr1 + (size_t)b * M * 2)
                               : (g_ctr2 + (size_t)b * M * 2);

    __shared__ float2 sxy[N];               // ORIGINAL order (winner lookup)
    __shared__ float spx[N], spy[N];        // sorted (init only)
    __shared__ unsigned short ssidx[N];     // sorted -> original idx
    __shared__ int counts[256], offs[256], cursor[256];
    __shared__ unsigned long long sVI[2][32];   // 32 slots, zero-padded

    // ---- load raw, publish original-order table ----
    float rx[P], ry[P];
    int cid[P];
#pragma unroll
    for (int k = 0; k < P; k++) {
        float2 v = p[tid + k * T];
        rx[k] = v.x; ry[k] = v.y;
        sxy[tid + k * T] = v;
    }
    if (tid < 256) counts[tid] = 0;
    if (tid < 64) sVI[tid >> 5][tid & 31] = 0ull;
    __syncthreads();
#pragma unroll
    for (int k = 0; k < P; k++) {
        int cx = (int)fminf(fmaxf((rx[k] - GRID_LO) * GRID_INV, 0.f), 15.f);
        int cy = (int)fminf(fmaxf((ry[k] - GRID_LO) * GRID_INV, 0.f), 15.f);
        cid[k] = cy * 16 + cx;
        atomicAdd(&counts[cid[k]], 1);
    }
    __syncthreads();
    if (tid < 256) offs[tid] = counts[tid];
    __syncthreads();
    for (int d = 1; d < 256; d <<= 1) {
        int v = 0;
        if (tid < 256 && tid >= d) v = offs[tid - d];
        __syncthreads();
        if (tid < 256 && tid >= d) offs[tid] += v;
        __syncthreads();
    }
    if (tid < 256) cursor[tid] = offs[tid] - counts[tid];
    __syncthreads();
#pragma unroll
    for (int k = 0; k < P; k++) {
        int pos = atomicAdd(&cursor[cid[k]], 1);
        spx[pos] = rx[k]; spy[pos] = ry[k];
        ssidx[pos] = (unsigned short)(tid + k * T);
    }
    __syncthreads();

    // ---- export bucket sort for SA pruning (one-time) ----
    for (int i = tid; i < N; i += T) {
        g_sxl[LEVEL][b][i] = spx[i];
        g_syl[LEVEL][b][i] = spy[i];
        g_sil[LEVEL][b][i] = ssidx[i];
    }
    if (tid < 256) g_cel[LEVEL][b][tid] = offs[tid];  // inclusive prefix = cell end

    // ---- registers: my sorted segment + warp bbox ----
    float px[P], py[P], md[P];
    unsigned sidx[P];
    float bx0 = 1e30f, bx1 = -1e30f, by0 = 1e30f, by1 = -1e30f;
    int base = tid * P;
#pragma unroll
    for (int k = 0; k < P; k++) {
        px[k] = spx[base + k]; py[k] = spy[base + k];
        sidx[k] = (unsigned)ssidx[base + k];
        md[k] = 1e10f;
        bx0 = fminf(bx0, px[k]); bx1 = fmaxf(bx1, px[k]);
        by0 = fminf(by0, py[k]); by1 = fmaxf(by1, py[k]);
    }
#pragma unroll
    for (int o = 16; o > 0; o >>= 1) {
        bx0 = fminf(bx0, __shfl_xor_sync(FULL, bx0, o));
        bx1 = fmaxf(bx1, __shfl_xor_sync(FULL, bx1, o));
        by0 = fminf(by0, __shfl_xor_sync(FULL, by0, o));
        by1 = fmaxf(by1, __shfl_xor_sync(FULL, by1, o));
    }
    __syncthreads();

    float2 c0 = sxy[0];
    float lx = c0.x, ly = c0.y;
    if (tid == 0) { cout[0] = lx; cout[1] = ly; }

    float wvf = 1e10f;          // cached warp max (uniform in warp)
    unsigned wi_ = 0u;          // cached warp argmin-idx among max

    for (int t = 1; t < M; t++) {
        float ex = fmaxf(fmaxf(bx0 - lx, lx - bx1), 0.f);
        float ey = fmaxf(fmaxf(by0 - ly, ly - by1), 0.f);
        float lb = fmaf(ex, ex, ey * ey);
        if (lb < wvf) {   // uniform per-warp branch (no divergence)
            float tb = -1.f;
#pragma unroll
            for (int k = 0; k < P; k++) {
                float dx = px[k] - lx, dy = py[k] - ly;
                float d2 = fmaf(dx, dx, dy * dy);
                md[k] = fminf(md[k], d2);
                tb = fmaxf(tb, md[k]);
            }
            unsigned bi = 0xFFFFFFFFu;
#pragma unroll
            for (int k = 0; k < P; k++)
                if (md[k] == tb && sidx[k] < bi) bi = sidx[k];
            unsigned vb = __float_as_uint(tb);
            unsigned wm = __reduce_max_sync(FULL, vb);
            unsigned cand = (vb == wm) ? bi : 0xFFFFFFFFu;
            wi_ = __reduce_min_sync(FULL, cand);
            wvf = __uint_as_float(wm);
        }
        int buf = t & 1;
        if (lane == 0)
            sVI[buf][wid] = ((unsigned long long)__float_as_uint(wvf) << 32) | wi_;
        __syncthreads();
        unsigned long long e = sVI[buf][lane];   // slots >= NW stay 0
        unsigned v2 = (unsigned)(e >> 32), i2 = (unsigned)e;
        unsigned m2 = __reduce_max_sync(FULL, v2);
        unsigned c2 = (v2 == m2) ? i2 : 0xFFFFFFFFu;
        unsigned gi = __reduce_min_sync(FULL, c2);
        float2 w = sxy[gi];          // broadcast LDS.64
        lx = w.x; ly = w.y;
        if (tid == 0) { cout[t * 2] = lx; cout[t * 2 + 1] = ly; }
    }
}

// ---------------- SA1: grid-pruned radius scan + max-aggregate ------------
// Scans only the <=2x2 grid cells overlapping the r=0.5 disk. The clamped
// cell mapping guarantees every in-radius point lies in a scanned cell.
__global__ void sa1_kernel(const float* __restrict__ c1W) {
    const int M = M1_, F = F1_;
    const float R = 0.5f, R2 = 0.25f;
    int i = blockIdx.x, b = blockIdx.y, tid = threadIdx.x;  // 64 threads
    __shared__ float sdx[MAXNBR], sdy[MAXNBR];
    __shared__ int   snb[MAXNBR];
    __shared__ int   scnt;
    if (tid == 0) scnt = 0;
    __syncthreads();
    float cx = g_ctr1[(b * M + i) * 2], cy = g_ctr1[(b * M + i) * 2 + 1];
    int ix0 = max(0, (int)((cx - R - GRID_LO) * GRID_INV));
    int ix1 = min(15, (int)((cx + R - GRID_LO) * GRID_INV));
    int iy0 = max(0, (int)((cy - R - GRID_LO) * GRID_INV));
    int iy1 = min(15, (int)((cy + R - GRID_LO) * GRID_INV));
    for (int gy = iy0; gy <= iy1; gy++) {
        int c0 = gy * 16 + ix0, c1 = gy * 16 + ix1;
        int s = (c0 == 0) ? 0 : g_cel[0][b][c0 - 1];
        int e = g_cel[0][b][c1];
        for (int j = s + tid; j < e; j += 64) {
            float dx = g_sxl[0][b][j] - cx;
            float dy = g_syl[0][b][j] - cy;
            float d2 = fmaf(dx, dx, dy * dy);
            if (d2 <= R2) {
                int s2 = atomicAdd(&scnt, 1);
                if (s2 < MAXNBR) {
                    snb[s2] = (int)g_sil[0][b][j];
                    sdx[s2] = dx; sdy[s2] = dy;
                }
            }
        }
    }
    __syncthreads();
    int cnt = min(scnt, MAXNBR);
    float wx = c1W[65 * 64 + tid];
    float wy = c1W[66 * 64 + tid];
    float mx = -1e9f;
    const float* pb = g_p1 + (size_t)b * N_ * F;
    int n = 0;
    for (; n + 4 <= cnt; n += 4) {
        float v0 = pb[snb[n] * F + tid];
        float v1 = pb[snb[n + 1] * F + tid];
        float v2 = pb[snb[n + 2] * F + tid];
        float v3 = pb[snb[n + 3] * F + tid];
        float m0 = fmaf(sdx[n], wx, fmaf(sdy[n], wy, v0));
        float m1 = fmaf(sdx[n + 1], wx, fmaf(sdy[n + 1], wy, v1));
        float m2 = fmaf(sdx[n + 2], wx, fmaf(sdy[n + 2], wy, v2));
        float m3 = fmaf(sdx[n + 3], wx, fmaf(sdy[n + 3], wy, v3));
        mx = fmaxf(mx, fmaxf(fmaxf(m0, m1), fmaxf(m2, m3)));
    }
    for (; n < cnt; n++) {
        float m = fmaf(sdx[n], wx, fmaf(sdy[n], wy, pb[snb[n] * F + tid]));
        mx = fmaxf(mx, m);
    }
    g_h1[((size_t)b * M + i) * F + tid] = mx;
}

// ---------------- p2[j] = h1_j @ c2W[:64] + c2b ---------------------------
__global__ void p2_kernel(const float* __restrict__ c2W, const float* __restrict__ c2b) {
    __shared__ float sW[64 * 128];
    __shared__ float sb[128];
    __shared__ float srow[64];
    int tid = threadIdx.x;  // 128
    for (int i = tid; i < 64 * 128; i += 128) sW[i] = c2W[i];
    sb[tid] = c2b[tid];
    __syncthreads();
    int row0 = blockIdx.x * 32;
    for (int r = 0; r < 32; r++) {
        int row = row0 + r;
        if (tid < 64) srow[tid] = g_h1[row * 64 + tid];
        __syncthreads();
        float acc = sb[tid];
#pragma unroll
        for (int c = 0; c < 64; c++) acc = fmaf(srow[c], sW[c * 128 + tid], acc);
        g_p2[row * 128 + tid] = acc;
        __syncthreads();
    }
}

// ---------------- SA2: grid-pruned (r=1.0 over ctr1 via FPS2's sort) ------
__global__ void sa2_kernel(const float* __restrict__ c2W) {
    const int M = M2_, F = F2_;
    const float R = 1.0f, R2 = 1.0f;
    int i = blockIdx.x, b = blockIdx.y, tid = threadIdx.x;  // 128
    __shared__ float sdx[MAXNBR], sdy[MAXNBR];
    __shared__ int   snb[MAXNBR];
    __shared__ int   scnt;
    if (tid == 0) scnt = 0;
    __syncthreads();
    float cx = g_ctr2[(b * M + i) * 2], cy = g_ctr2[(b * M + i) * 2 + 1];
    int ix0 = max(0, (int)((cx - R - GRID_LO) * GRID_INV));
    int ix1 = min(15, (int)((cx + R - GRID_LO) * GRID_INV));
    int iy0 = max(0, (int)((cy - R - GRID_LO) * GRID_INV));
    int iy1 = min(15, (int)((cy + R - GRID_LO) * GRID_INV));
    for (int gy = iy0; gy <= iy1; gy++) {
        int c0 = gy * 16 + ix0, c1 = gy * 16 + ix1;
        int s = (c0 == 0) ? 0 : g_cel[1][b][c0 - 1];
        int e = g_cel[1][b][c1];
        for (int j = s + tid; j < e; j += F) {
            float dx = g_sxl[1][b][j] - cx;
            float dy = g_syl[1][b][j] - cy;
            float d2 = fmaf(dx, dx, dy * dy);
            if (d2 <= R2) {
                int s2 = atomicAdd(&scnt, 1);
                if (s2 < MAXNBR) {
                    snb[s2] = (int)g_sil[1][b][j];
                    sdx[s2] = dx; sdy[s2] = dy;
                }
            }
        }
    }
    __syncthreads();
    int cnt = min(scnt, MAXNBR);
    float wx = c2W[64 * 128 + tid];
    float wy = c2W[65 * 128 + tid];
    float mx = -1e9f;
    const float* pb = g_p2 + (size_t)b * M1_ * F;
    int n = 0;
    for (; n + 4 <= cnt; n += 4) {
        float v0 = pb[snb[n] * F + tid];
        float v1 = pb[snb[n + 1] * F + tid];
        float v2 = pb[snb[n + 2] * F + tid];
        float v3 = pb[snb[n + 3] * F + tid];
        float m0 = fmaf(sdx[n], wx, fmaf(sdy[n], wy, v0));
        float m1 = fmaf(sdx[n + 1], wx, fmaf(sdy[n + 1], wy, v1));
        float m2 = fmaf(sdx[n + 2], wx, fmaf(sdy[n + 2], wy, v2));
        float m3 = fmaf(sdx[n + 3], wx, fmaf(sdy[n + 3], wy, v3));
        mx = fmaxf(mx, fmaxf(fmaxf(m0, m1), fmaxf(m2, m3)));
    }
    for (; n < cnt; n++) {
        float m = fmaf(sdx[n], wx, fmaf(sdy[n], wy, pb[snb[n] * F + tid]));
        mx = fmaxf(mx, m);
    }
    g_h2[((size_t)b * M + i) * F + tid] = mx;
}

// ---------------- final projection + partial max pool ---------------------
__global__ void final_partial(const float* __restrict__ W, const float* __restrict__ bias) {
    int fchunk = blockIdx.x, rchunk = blockIdx.y, b = blockIdx.z;
    int tid = threadIdx.x;  // 128
    int f = fchunk * 128 + tid;
    __shared__ float sh[64][132];
    int r0 = rchunk * 64;
    for (int e = tid; e < 64 * 130; e += 128) {
        int r = e / 130, c = e % 130;
        float v;
        if (c < 128) v = g_h2[((size_t)b * M2_ + r0 + r) * 128 + c];
        else         v = g_ctr2[(b * M2_ + r0 + r) * 2 + (c - 128)];
        sh[r][c] = v;
    }
    __syncthreads();
    float acc[64];
#pragma unroll
    for (int r = 0; r < 64; r++) acc[r] = 0.0f;
    for (int c = 0; c < 130; c++) {
        float w = W[c * 1024 + f];
#pragma unroll
        for (int r = 0; r < 64; r++) acc[r] = fmaf(sh[r][c], w, acc[r]);
    }
    float mx = acc[0];
#pragma unroll
    for (int r = 1; r < 64; r++) mx = fmaxf(mx, acc[r]);
    g_pmax[(b * 8 + rchunk) * 1024 + f] = mx + bias[f];
}

__global__ void final_reduce(float* __restrict__ gf) {
    int b = blockIdx.x, f = threadIdx.x;  // 1024
    float mx = g_pmax[(b * 8) * 1024 + f];
#pragma unroll
    for (int r = 1; r < 8; r++) mx = fmaxf(mx, g_pmax[(b * 8 + r) * 1024 + f]);
    gf[b * 1024 + f] = mx;
}

// ---------------- launch ---------------------------------------------------
extern "C" void kernel_launch(void* const* d_in, const int* in_sizes, int n_in,
                              void* d_out, int out_size) {
    const float* x     = (const float*)d_in[0];
    const float* zones = (const float*)d_in[1];
    const float* lf_W1 = (const float*)d_in[2];
    const float* lf_b1 = (const float*)d_in[3];
    const float* lf_W2 = (const float*)d_in[4];
    const float* lf_b2 = (const float*)d_in[5];
    const float* c1_W  = (const float*)d_in[6];
    const float* c1_b  = (const float*)d_in[7];
    const float* c2_W  = (const float*)d_in[8];
    const float* c2_b  = (const float*)d_in[9];
    const float* c3_W  = (const float*)d_in[10];
    const float* c3_b  = (const float*)d_in[11];

    float* lf_out = (float*)d_out;
    float* gf_out = (float*)d_out + (size_t)B_ * N_ * LF_;

    fps_kernel<1024, 4, N_, M1_, 0><<<B_, 1024>>>(x);       // FPS level 1
    lfp1_kernel<<<(B_ * N_) / 32, 64>>>(x, zones, lf_W1, lf_b1, lf_W2, lf_b2,
                                        c1_W, c1_b, lf_out);
    fps_kernel<512, 4, M1_, M2_, 1><<<B_, 512>>>(nullptr);  // FPS level 2
    sa1_kernel<<<dim3(M1_, B_), 64>>>(c1_W);
    p2_kernel<<<(B_ * M1_) / 32, 128>>>(c2_W, c2_b);
    sa2_kernel<<<dim3(M2_, B_), F2_>>>(c2_W);
    final_partial<<<dim3(8, 8, B_), 128>>>(c3_W, c3_b);
    final_reduce<<<B_, 1024>>>(gf_out);
}

// round 13
// speedup vs baseline: 1.4544x; 1.0100x over previous
#include <cuda_runtime.h>
#include <cuda_bf16.h>
#include <cstdint>

#define B_  4
#define N_  4096
#define M1_ 2048
#define M2_ 512
#define F1_ 64
#define F2_ 128
#define F3_ 1024
#define LF_ 64
#define MAXNBR 128

// grid constants (fixed range, row-major cells) shared by FPS and SA pruning
#define GRID_LO   (-18.0f)
#define GRID_INV  (16.0f / 36.0f)

// ---------------- device scratch ----------------
__device__ float g_p1  [B_ * N_  * F1_];
__device__ float g_h1  [B_ * M1_ * F1_];
__device__ float g_ctr1[B_ * M1_ * 2];
__device__ float g_p2  [B_ * M1_ * F2_];
__device__ float g_h2  [B_ * M2_ * F2_];
__device__ float g_ctr2[B_ * M2_ * 2];
__device__ float g_pmax[B_ * 8 * F3_];
// exported bucket sort (level 0: x points, level 1: ctr1 points)
__device__ float          g_sxl[2][B_][N_];
__device__ float          g_syl[2][B_][N_];
__device__ unsigned short g_sil[2][B_][N_];
__device__ int            g_cel[2][B_][256];

// ------ fused: lf = tanh(tanh(x W1+b1) W2+b2);  p1 = [lf,z] @ c1W[:65]+c1b
__global__ void lfp1_kernel(const float* __restrict__ x, const float* __restrict__ zones,
                            const float* __restrict__ W1, const float* __restrict__ b1,
                            const float* __restrict__ W2, const float* __restrict__ b2,
                            const float* __restrict__ c1W, const float* __restrict__ c1b,
                            float* __restrict__ lf_out) {
    __shared__ float sW2[64 * 64];
    __shared__ float sWc[65 * 64];
    __shared__ float sW1[2 * 64];
    __shared__ float sb1[64], sb2[64], sbc[64];
    __shared__ float st1[64], slf[64];
    int tid = threadIdx.x;  // 64
    for (int i = tid; i < 64 * 64; i += 64) sW2[i] = W2[i];
    for (int i = tid; i < 65 * 64; i += 64) sWc[i] = c1W[i];
    sW1[tid] = W1[tid]; sW1[64 + tid] = W1[64 + tid];
    sb1[tid] = b1[tid]; sb2[tid] = b2[tid]; sbc[tid] = c1b[tid];
    __syncthreads();
    int row0 = blockIdx.x * 32;
    for (int r = 0; r < 32; r++) {
        int row = row0 + r;
        float x0 = x[row * 2], x1 = x[row * 2 + 1];
        float t1 = tanhf(x0 * sW1[tid] + x1 * sW1[64 + tid] + sb1[tid]);
        st1[tid] = t1;
        __syncthreads();
        float acc = sb2[tid];
#pragma unroll
        for (int c = 0; c < 64; c++) acc = fmaf(st1[c], sW2[c * 64 + tid], acc);
        float lf = tanhf(acc);
        lf_out[row * 64 + tid] = lf;
        slf[tid] = lf;
        __syncthreads();
        float z = zones[row];
        float acc2 = fmaf(z, sWc[64 * 64 + tid], sbc[tid]);
#pragma unroll
        for (int c = 0; c < 64; c++) acc2 = fmaf(slf[c], sWc[c * 64 + tid], acc2);
        g_p1[row * 64 + tid] = acc2;
        __syncthreads();
    }
}

// ---------------- FPS: bucketed + warp bbox prune + redundant redux merge --
// R6 chain with a split merge tuple: per-warp (max value: float[32],
// argmin-orig-idx: ushort[32]) -> 192 B/warp merge traffic instead of 256 B.
// Values are md >= 0, so float order == uint-bits order; padded slots hold
// (0.0f, 0xFFFF): a pad lane only qualifies when the true max is 0.0f, in
// which case real lanes (idx < 4096) also qualify and win the redux_min.
// Exact vs jnp.argmax: skipped warp updates are provably no-ops (bbox lower
// bound >= cached warp max); all reductions are (max value, min ORIGINAL
// index) -> identical first-occurrence winner.
// Exports the bucket sort for SA grid pruning.
template <int T, int P, int N, int M, int LEVEL>
__global__ __launch_bounds__(T, 1) void fps_kernel(const float* __restrict__ pos_in) {
    const unsigned FULL = 0xFFFFFFFFu;
    int b = blockIdx.x;
    int tid = threadIdx.x;
    int wid = tid >> 5, lane = tid & 31;
    const float2* p = (LEVEL == 0) ? (const float2*)(pos_in + (size_t)b * N * 2)
                                   : (const float2*)(g_ctr1 + (size_t)b * N * 2);
    float* cout = (LEVEL == 0) ? (g_ctr1 + (size_t)b * M * 2)
                               : (g_ctr2 + (size_t)b * M * 2);

    __shared__ float2 sxy[N];               // ORIGINAL order (winner lookup)
    __shared__ float spx[N], spy[N];        // sorted (init only)
    __shared__ unsigned short ssidx[N];     // sorted -> original idx
    __shared__ int counts[256], offs[256], cursor[256];
    __shared__ float          sVv[2][32];   // per-warp max value (zero-padded)
    __shared__ unsigned short sVi[2][32];   // per-warp argmin idx (0xFFFF-padded)

    // ---- load raw, publish original-order table ----
    float rx[P], ry[P];
    int cid[P];
#pragma unroll
    for (int k = 0; k < P; k++) {
        float2 v = p[tid + k * T];
        rx[k] = v.x; ry[k] = v.y;
        sxy[tid + k * T] = v;
    }
    if (tid < 256) counts[tid] = 0;
    if (tid < 64) { sVv[tid >> 5][tid & 31] = 0.0f; sVi[tid >> 5][tid & 31] = 0xFFFFu; }
    __syncthreads();
#pragma unroll
    for (int k = 0; k < P; k++) {
        int cx = (int)fminf(fmaxf((rx[k] - GRID_LO) * GRID_INV, 0.f), 15.f);
        int cy = (int)fminf(fmaxf((ry[k] - GRID_LO) * GRID_INV, 0.f), 15.f);
        cid[k] = cy * 16 + cx;
        atomicAdd(&counts[cid[k]], 1);
    }
    __syncthreads();
    if (tid < 256) offs[tid] = counts[tid];
    __syncthreads();
    for (int d = 1; d < 256; d <<= 1) {
        int v = 0;
        if (tid < 256 && tid >= d) v = offs[tid - d];
        __syncthreads();
        if (tid < 256 && tid >= d) offs[tid] += v;
        __syncthreads();
    }
    if (tid < 256) cursor[tid] = offs[tid] - counts[tid];
    __syncthreads();
#pragma unroll
    for (int k = 0; k < P; k++) {
        int pos = atomicAdd(&cursor[cid[k]], 1);
        spx[pos] = rx[k]; spy[pos] = ry[k];
        ssidx[pos] = (unsigned short)(tid + k * T);
    }
    __syncthreads();

    // ---- export bucket sort for SA pruning (one-time) ----
    for (int i = tid; i < N; i += T) {
        g_sxl[LEVEL][b][i] = spx[i];
        g_syl[LEVEL][b][i] = spy[i];
        g_sil[LEVEL][b][i] = ssidx[i];
    }
    if (tid < 256) g_cel[LEVEL][b][tid] = offs[tid];  // inclusive prefix = cell end

    // ---- registers: my sorted segment + warp bbox ----
    float px[P], py[P], md[P];
    unsigned sidx[P];
    float bx0 = 1e30f, bx1 = -1e30f, by0 = 1e30f, by1 = -1e30f;
    int base = tid * P;
#pragma unroll
    for (int k = 0; k < P; k++) {
        px[k] = spx[base + k]; py[k] = spy[base + k];
        sidx[k] = (unsigned)ssidx[base + k];
        md[k] = 1e10f;
        bx0 = fminf(bx0, px[k]); bx1 = fmaxf(bx1, px[k]);
        by0 = fminf(by0, py[k]); by1 = fmaxf(by1, py[k]);
    }
#pragma unroll
    for (int o = 16; o > 0; o >>= 1) {
        bx0 = fminf(bx0, __shfl_xor_sync(FULL, bx0, o));
        bx1 = fmaxf(bx1, __shfl_xor_sync(FULL, bx1, o));
        by0 = fminf(by0, __shfl_xor_sync(FULL, by0, o));
        by1 = fmaxf(by1, __shfl_xor_sync(FULL, by1, o));
    }
    __syncthreads();

    float2 c0 = sxy[0];
    float lx = c0.x, ly = c0.y;
    if (tid == 0) { cout[0] = lx; cout[1] = ly; }

    float wvf = 1e10f;          // cached warp max (uniform in warp)
    unsigned wi_ = 0u;          // cached warp argmin-idx among max

    for (int t = 1; t < M; t++) {
        float ex = fmaxf(fmaxf(bx0 - lx, lx - bx1), 0.f);
        float ey = fmaxf(fmaxf(by0 - ly, ly - by1), 0.f);
        float lb = fmaf(ex, ex, ey * ey);
        if (lb < wvf) {   // uniform per-warp branch (no divergence)
            float tb = -1.f;
#pragma unroll
            for (int k = 0; k < P; k++) {
                float dx = px[k] - lx, dy = py[k] - ly;
                float d2 = fmaf(dx, dx, dy * dy);
                md[k] = fminf(md[k], d2);
                tb = fmaxf(tb, md[k]);
            }
            unsigned bi = 0xFFFFFFFFu;
#pragma unroll
            for (int k = 0; k < P; k++)
                if (md[k] == tb && sidx[k] < bi) bi = sidx[k];
            unsigned vb = __float_as_uint(tb);
            unsigned wm = __reduce_max_sync(FULL, vb);
            unsigned cand = (vb == wm) ? bi : 0xFFFFFFFFu;
            wi_ = __reduce_min_sync(FULL, cand);
            wvf = __uint_as_float(wm);
        }
        int buf = t & 1;
        if (lane == 0) {
            sVv[buf][wid] = wvf;
            sVi[buf][wid] = (unsigned short)wi_;
        }
        __syncthreads();
        float v2f = sVv[buf][lane];              // pad slots: 0.0f
        unsigned i2 = (unsigned)sVi[buf][lane];  // pad slots: 0xFFFF
        unsigned v2 = __float_as_uint(v2f);
        unsigned m2 = __reduce_max_sync(FULL, v2);
        unsigned c2 = (v2 == m2) ? i2 : 0xFFFFFFFFu;
        unsigned gi = __reduce_min_sync(FULL, c2);
        float2 w = sxy[gi];          // broadcast LDS.64
        lx = w.x; ly = w.y;
        if (tid == 0) { cout[t * 2] = lx; cout[t * 2 + 1] = ly; }
    }
}

// ---------------- SA1: grid-pruned radius scan + max-aggregate ------------
// Scans only the <=2x2 grid cells overlapping the r=0.5 disk. The clamped
// cell mapping guarantees every in-radius point lies in a scanned cell.
__global__ void sa1_kernel(const float* __restrict__ c1W) {
    const int M = M1_, F = F1_;
    const float R = 0.5f, R2 = 0.25f;
    int i = blockIdx.x, b = blockIdx.y, tid = threadIdx.x;  // 64 threads
    __shared__ float sdx[MAXNBR], sdy[MAXNBR];
    __shared__ int   snb[MAXNBR];
    __shared__ int   scnt;
    if (tid == 0) scnt = 0;
    __syncthreads();
    float cx = g_ctr1[(b * M + i) * 2], cy = g_ctr1[(b * M + i) * 2 + 1];
    int ix0 = max(0, (int)((cx - R - GRID_LO) * GRID_INV));
    int ix1 = min(15, (int)((cx + R - GRID_LO) * GRID_INV));
    int iy0 = max(0, (int)((cy - R - GRID_LO) * GRID_INV));
    int iy1 = min(15, (int)((cy + R - GRID_LO) * GRID_INV));
    for (int gy = iy0; gy <= iy1; gy++) {
        int c0 = gy * 16 + ix0, c1 = gy * 16 + ix1;
        int s = (c0 == 0) ? 0 : g_cel[0][b][c0 - 1];
        int e = g_cel[0][b][c1];
        for (int j = s + tid; j < e; j += 64) {
            float dx = g_sxl[0][b][j] - cx;
            float dy = g_syl[0][b][j] - cy;
            float d2 = fmaf(dx, dx, dy * dy);
            if (d2 <= R2) {
                int s2 = atomicAdd(&scnt, 1);
                if (s2 < MAXNBR) {
                    snb[s2] = (int)g_sil[0][b][j];
                    sdx[s2] = dx; sdy[s2] = dy;
                }
            }
        }
    }
    __syncthreads();
    int cnt = min(scnt, MAXNBR);
    float wx = c1W[65 * 64 + tid];
    float wy = c1W[66 * 64 + tid];
    float mx = -1e9f;
    const float* pb = g_p1 + (size_t)b * N_ * F;
    int n = 0;
    for (; n + 4 <= cnt; n += 4) {
        float v0 = pb[snb[n] * F + tid];
        float v1 = pb[snb[n + 1] * F + tid];
        float v2 = pb[snb[n + 2] * F + tid];
        float v3 = pb[snb[n + 3] * F + tid];
        float m0 = fmaf(sdx[n], wx, fmaf(sdy[n], wy, v0));
        float m1 = fmaf(sdx[n + 1], wx, fmaf(sdy[n + 1], wy, v1));
        float m2 = fmaf(sdx[n + 2], wx, fmaf(sdy[n + 2], wy, v2));
        float m3 = fmaf(sdx[n + 3], wx, fmaf(sdy[n + 3], wy, v3));
        mx = fmaxf(mx, fmaxf(fmaxf(m0, m1), fmaxf(m2, m3)));
    }
    for (; n < cnt; n++) {
        float m = fmaf(sdx[n], wx, fmaf(sdy[n], wy, pb[snb[n] * F + tid]));
        mx = fmaxf(mx, m);
    }
    g_h1[((size_t)b * M + i) * F + tid] = mx;
}

// ---------------- p2[j] = h1_j @ c2W[:64] + c2b ---------------------------
__global__ void p2_kernel(const float* __restrict__ c2W, const float* __restrict__ c2b) {
    __shared__ float sW[64 * 128];
    __shared__ float sb[128];
    __shared__ float srow[64];
    int tid = threadIdx.x;  // 128
    for (int i = tid; i < 64 * 128; i += 128) sW[i] = c2W[i];
    sb[tid] = c2b[tid];
    __syncthreads();
    int row0 = blockIdx.x * 32;
    for (int r = 0; r < 32; r++) {
        int row = row0 + r;
        if (tid < 64) srow[tid] = g_h1[row * 64 + tid];
        __syncthreads();
        float acc = sb[tid];
#pragma unroll
        for (int c = 0; c < 64; c++) acc = fmaf(srow[c], sW[c * 128 + tid], acc);
        g_p2[row * 128 + tid] = acc;
        __syncthreads();
    }
}

// ---------------- SA2: grid-pruned (r=1.0 over ctr1 via FPS2's sort) ------
__global__ void sa2_kernel(const float* __restrict__ c2W) {
    const int M = M2_, F = F2_;
    const float R = 1.0f, R2 = 1.0f;
    int i = blockIdx.x, b = blockIdx.y, tid = threadIdx.x;  // 128
    __shared__ float sdx[MAXNBR], sdy[MAXNBR];
    __shared__ int   snb[MAXNBR];
    __shared__ int   scnt;
    if (tid == 0) scnt = 0;
    __syncthreads();
    float cx = g_ctr2[(b * M + i) * 2], cy = g_ctr2[(b * M + i) * 2 + 1];
    int ix0 = max(0, (int)((cx - R - GRID_LO) * GRID_INV));
    int ix1 = min(15, (int)((cx + R - GRID_LO) * GRID_INV));
    int iy0 = max(0, (int)((cy - R - GRID_LO) * GRID_INV));
    int iy1 = min(15, (int)((cy + R - GRID_LO) * GRID_INV));
    for (int gy = iy0; gy <= iy1; gy++) {
        int c0 = gy * 16 + ix0, c1 = gy * 16 + ix1;
        int s = (c0 == 0) ? 0 : g_cel[1][b][c0 - 1];
        int e = g_cel[1][b][c1];
        for (int j = s + tid; j < e; j += F) {
            float dx = g_sxl[1][b][j] - cx;
            float dy = g_syl[1][b][j] - cy;
            float d2 = fmaf(dx, dx, dy * dy);
            if (d2 <= R2) {
                int s2 = atomicAdd(&scnt, 1);
                if (s2 < MAXNBR) {
                    snb[s2] = (int)g_sil[1][b][j];
                    sdx[s2] = dx; sdy[s2] = dy;
                }
            }
        }
    }
    __syncthreads();
    int cnt = min(scnt, MAXNBR);
    float wx = c2W[64 * 128 + tid];
    float wy = c2W[65 * 128 + tid];
    float mx = -1e9f;
    const float* pb = g_p2 + (size_t)b * M1_ * F;
    int n = 0;
    for (; n + 4 <= cnt; n += 4) {
        float v0 = pb[snb[n] * F + tid];
        float v1 = pb[snb[n + 1] * F + tid];
        float v2 = pb[snb[n + 2] * F + tid];
        float v3 = pb[snb[n + 3] * F + tid];
        float m0 = fmaf(sdx[n], wx, fmaf(sdy[n], wy, v0));
        float m1 = fmaf(sdx[n + 1], wx, fmaf(sdy[n + 1], wy, v1));
        float m2 = fmaf(sdx[n + 2], wx, fmaf(sdy[n + 2], wy, v2));
        float m3 = fmaf(sdx[n + 3], wx, fmaf(sdy[n + 3], wy, v3));
        mx = fmaxf(mx, fmaxf(fmaxf(m0, m1), fmaxf(m2, m3)));
    }
    for (; n < cnt; n++) {
        float m = fmaf(sdx[n], wx, fmaf(sdy[n], wy, pb[snb[n] * F + tid]));
        mx = fmaxf(mx, m);
    }
    g_h2[((size_t)b * M + i) * F + tid] = mx;
}

// ---------------- final projection + partial max pool ---------------------
__global__ void final_partial(const float* __restrict__ W, const float* __restrict__ bias) {
    int fchunk = blockIdx.x, rchunk = blockIdx.y, b = blockIdx.z;
    int tid = threadIdx.x;  // 128
    int f = fchunk * 128 + tid;
    __shared__ float sh[64][132];
    int r0 = rchunk * 64;
    for (int e = tid; e < 64 * 130; e += 128) {
        int r = e / 130, c = e % 130;
        float v;
        if (c < 128) v = g_h2[((size_t)b * M2_ + r0 + r) * 128 + c];
        else         v = g_ctr2[(b * M2_ + r0 + r) * 2 + (c - 128)];
        sh[r][c] = v;
    }
    __syncthreads();
    float acc[64];
#pragma unroll
    for (int r = 0; r < 64; r++) acc[r] = 0.0f;
    for (int c = 0; c < 130; c++) {
        float w = W[c * 1024 + f];
#pragma unroll
        for (int r = 0; r < 64; r++) acc[r] = fmaf(sh[r][c], w, acc[r]);
    }
    float mx = acc[0];
#pragma unroll
    for (int r = 1; r < 64; r++) mx = fmaxf(mx, acc[r]);
    g_pmax[(b * 8 + rchunk) * 1024 + f] = mx + bias[f];
}

__global__ void final_reduce(float* __restrict__ gf) {
    int b = blockIdx.x, f = threadIdx.x;  // 1024
    float mx = g_pmax[(b * 8) * 1024 + f];
#pragma unroll
    for (int r = 1; r < 8; r++) mx = fmaxf(mx, g_pmax[(b * 8 + r) * 1024 + f]);
    gf[b * 1024 + f] = mx;
}

// ---------------- launch ---------------------------------------------------
extern "C" void kernel_launch(void* const* d_in, const int* in_sizes, int n_in,
                              void* d_out, int out_size) {
    const float* x     = (const float*)d_in[0];
    const float* zones = (const float*)d_in[1];
    const float* lf_W1 = (const float*)d_in[2];
    const float* lf_b1 = (const float*)d_in[3];
    const float* lf_W2 = (const float*)d_in[4];
    const float* lf_b2 = (const float*)d_in[5];
    const float* c1_W  = (const float*)d_in[6];
    const float* c1_b  = (const float*)d_in[7];
    const float* c2_W  = (const float*)d_in[8];
    const float* c2_b  = (const float*)d_in[9];
    const float* c3_W  = (const float*)d_in[10];
    const float* c3_b  = (const float*)d_in[11];

    float* lf_out = (float*)d_out;
    float* gf_out = (float*)d_out + (size_t)B_ * N_ * LF_;

    fps_kernel<1024, 4, N_, M1_, 0><<<B_, 1024>>>(x);       // FPS level 1
    lfp1_kernel<<<(B_ * N_) / 32, 64>>>(x, zones, lf_W1, lf_b1, lf_W2, lf_b2,
                                        c1_W, c1_b, lf_out);
    fps_kernel<512, 4, M1_, M2_, 1><<<B_, 512>>>(nullptr);  // FPS level 2
    sa1_kernel<<<dim3(M1_, B_), 64>>>(c1_W);
    p2_kernel<<<(B_ * M1_) / 32, 128>>>(c2_W, c2_b);
    sa2_kernel<<<dim3(M2_, B_), F2_>>>(c2_W);
    final_partial<<<dim3(8, 8, B_), 128>>>(c3_W, c3_b);
    final_reduce<<<B_, 1024>>>(gf_out);
}